// round 12
// baseline (speedup 1.0000x reference)
#include <cuda_runtime.h>
#include <math.h>

#define NB 256
#define TT 1000
#define KD 128
#define VD 128
#define ED 256
#define HD 512
#define ML 250
#define VOC 30
#define NCTA 296
#define NTHR 256
#define PSZ1 ((size_t)NB*2048)
#define PSZ3 ((size_t)NB*512)

typedef unsigned long long ull;

__device__ __align__(16) float g_embs[(size_t)ML*NB*ED];
__device__ __align__(16) float g_h1[NB*HD], g_c1[NB*HD];
__device__ __align__(16) float g_h2[NB*HD], g_c2[NB*HD];
__device__ __align__(16) float g_h3[NB*KD], g_c3[NB*KD];
__device__ __align__(16) float g_ctx[NB*VD];
__device__ __align__(16) float g_linWT[(KD+VD)*KD];
__device__ __align__(16) float gp1[4*PSZ1];
__device__ __align__(16) float gp2[4*PSZ1];
__device__ __align__(16) float gp3[8*PSZ3];
__device__ unsigned g_grp[8*32];
__device__ unsigned g_root, g_gen;

// ---- two-level grid barrier: 8 groups of 37 + root ----
__device__ __forceinline__ void gridbar() {
    __syncthreads();
    if (threadIdx.x == 0) {
        unsigned snap = *(volatile unsigned*)&g_gen;
        __threadfence();
        unsigned a = atomicAdd(&g_grp[(blockIdx.x & 7) * 32], 1u);
        if (a == 36u) {
            unsigned r = atomicAdd(&g_root, 1u);
            if (r == 7u) {
                #pragma unroll
                for (int i = 0; i < 8; ++i) g_grp[i*32] = 0u;
                g_root = 0u;
                __threadfence();
                atomicAdd(&g_gen, 1u);
            }
        }
        while (*(volatile unsigned*)&g_gen == snap) __nanosleep(32);
        __threadfence();
    }
    __syncthreads();
}

__device__ __forceinline__ ull packdup(float x) {
    ull r;
    asm("mov.b64 %0, {%1, %1};" : "=l"(r) : "r"(__float_as_uint(x)));
    return r;
}
__device__ __forceinline__ void ffma2(ull& d, ull a, ull b) {
    asm("fma.rn.f32x2 %0, %1, %2, %0;" : "+l"(d) : "l"(a), "l"(b));
}
__device__ __forceinline__ float2 unpack2(ull v) {
    unsigned lo, hi;
    asm("mov.b64 {%0, %1}, %2;" : "=r"(lo), "=r"(hi) : "l"(v));
    float2 f; f.x = __uint_as_float(lo); f.y = __uint_as_float(hi);
    return f;
}
__device__ __forceinline__ float sigf(float x) { return 1.f/(1.f + expf(-x)); }

struct Seg { const float* A; int lda; const float* W; int ldw; int K; };

__device__ __forceinline__ void resolve(const Seg* segs, int nseg, int kb,
                                        const float*& Ap, int& la,
                                        const float*& Wp, int& lw) {
    Ap = segs[0].A; la = segs[0].lda; Wp = segs[0].W; lw = segs[0].ldw;
    int base = 0;
    for (int q = 0; q < nseg; ++q) {
        if (kb >= base && kb < base + segs[q].K) {
            Ap = segs[q].A + (kb - base); la = segs[q].lda;
            Wp = segs[q].W + (kb - base); lw = segs[q].ldw;
        }
        base += segs[q].K;
    }
}

// ---- split-K GEMM: BM=128, BN=64, per-thread 8x4, FFMA2, reg double-buffer ----
__device__ void gemm_part(const Seg* segs, int nseg, int Ncols, int Ktot,
                          float* dstbase, size_t psz, int spl, float* s_mem)
{
    const int nt = Ncols >> 6;          // tiles along N (BN=64)
    const int tiles = 2*nt;             // M=256 -> 2 m-tiles
    const int local = blockIdx.x;
    if (local >= tiles*spl) return;
    const int s  = local / tiles;
    const int rem = local - s*tiles;
    const int m0 = (rem / nt) * 128;
    const int j0 = (rem % nt) * 64;
    const int nbt = Ktot >> 5;
    const int b0 = (nbt*s)/spl, b1 = (nbt*(s+1))/spl;

    float* As = s_mem;                  // [32][132]
    float* Ws = s_mem + 32*132;         // [32][68]
    const int tid = threadIdx.x;
    const int tx = tid & 15, ty = tid >> 4;

    ull acc[8][2];
    #pragma unroll
    for (int i = 0; i < 8; ++i) { acc[i][0] = 0ull; acc[i][1] = 0ull; }

    float4 pa[4], pw[2];

    if (b0 < b1) {      // prefetch first block
        const float* Ap; int la; const float* Wp; int lw;
        resolve(segs, nseg, b0 << 5, Ap, la, Wp, lw);
        #pragma unroll
        for (int it = 0; it < 4; ++it) {
            int q = tid + (it << 8); int m = q >> 3, kq = q & 7;
            pa[it] = *(const float4*)(Ap + (size_t)(m0+m)*la + (kq << 2));
        }
        #pragma unroll
        for (int it = 0; it < 2; ++it) {
            int q = tid + (it << 8); int j = q >> 3, kq = q & 7;
            pw[it] = *(const float4*)(Wp + (size_t)(j0+j)*lw + (kq << 2));
        }
    }

    for (int b = b0; b < b1; ++b) {
        __syncthreads();
        #pragma unroll
        for (int it = 0; it < 4; ++it) {     // A tile -> smem (transposed)
            int q = tid + (it << 8); int m = q >> 3, kq = q & 7;
            As[(kq*4+0)*132 + m] = pa[it].x;
            As[(kq*4+1)*132 + m] = pa[it].y;
            As[(kq*4+2)*132 + m] = pa[it].z;
            As[(kq*4+3)*132 + m] = pa[it].w;
        }
        #pragma unroll
        for (int it = 0; it < 2; ++it) {     // W tile -> smem (transposed)
            int q = tid + (it << 8); int j = q >> 3, kq = q & 7;
            Ws[(kq*4+0)*68 + j] = pw[it].x;
            Ws[(kq*4+1)*68 + j] = pw[it].y;
            Ws[(kq*4+2)*68 + j] = pw[it].z;
            Ws[(kq*4+3)*68 + j] = pw[it].w;
        }
        __syncthreads();

        if (b + 1 < b1) {   // prefetch next block during compute
            const float* Ap; int la; const float* Wp; int lw;
            resolve(segs, nseg, (b+1) << 5, Ap, la, Wp, lw);
            #pragma unroll
            for (int it = 0; it < 4; ++it) {
                int q = tid + (it << 8); int m = q >> 3, kq = q & 7;
                pa[it] = *(const float4*)(Ap + (size_t)(m0+m)*la + (kq << 2));
            }
            #pragma unroll
            for (int it = 0; it < 2; ++it) {
                int q = tid + (it << 8); int j = q >> 3, kq = q & 7;
                pw[it] = *(const float4*)(Wp + (size_t)(j0+j)*lw + (kq << 2));
            }
        }

        #pragma unroll 8
        for (int k = 0; k < 32; ++k) {
            float4 a0 = *(const float4*)&As[k*132 + ty*8];
            float4 a1 = *(const float4*)&As[k*132 + ty*8 + 4];
            ull da0 = packdup(a0.x), da1 = packdup(a0.y);
            ull da2 = packdup(a0.z), da3 = packdup(a0.w);
            ull da4 = packdup(a1.x), da5 = packdup(a1.y);
            ull da6 = packdup(a1.z), da7 = packdup(a1.w);
            float4 w0 = *(const float4*)&Ws[k*68 + tx*4];
            const ull* wp = (const ull*)&w0;
            ffma2(acc[0][0], wp[0], da0); ffma2(acc[0][1], wp[1], da0);
            ffma2(acc[1][0], wp[0], da1); ffma2(acc[1][1], wp[1], da1);
            ffma2(acc[2][0], wp[0], da2); ffma2(acc[2][1], wp[1], da2);
            ffma2(acc[3][0], wp[0], da3); ffma2(acc[3][1], wp[1], da3);
            ffma2(acc[4][0], wp[0], da4); ffma2(acc[4][1], wp[1], da4);
            ffma2(acc[5][0], wp[0], da5); ffma2(acc[5][1], wp[1], da5);
            ffma2(acc[6][0], wp[0], da6); ffma2(acc[6][1], wp[1], da6);
            ffma2(acc[7][0], wp[0], da7); ffma2(acc[7][1], wp[1], da7);
        }
    }

    float* dst = dstbase + (size_t)s*psz;
    #pragma unroll
    for (int i = 0; i < 8; ++i) {
        int m = m0 + ty*8 + i;
        int j = j0 + tx*4;
        float2 v0 = unpack2(acc[i][0]), v1 = unpack2(acc[i][1]);
        *(float4*)&dst[(size_t)m*Ncols + j] = make_float4(v0.x, v0.y, v1.x, v1.y);
    }
}

// ---- cell: gates = sum of nspl partials + biases -> LSTM update ----
__device__ void cell_sum(int H, const float* __restrict__ buf, int nspl, size_t psz,
                         const float* __restrict__ b_ih, const float* __restrict__ b_hh,
                         float* __restrict__ hst, float* __restrict__ cst)
{
    const int Ncols = 4*H;
    const int gid = blockIdx.x*NTHR + threadIdx.x;
    const int hq = H >> 2;
    for (int q = gid; q < NB*hq; q += NCTA*NTHR) {
        int n = q / hq, j = (q - n*hq) << 2;
        float4 gs[4];
        #pragma unroll
        for (int g = 0; g < 4; ++g) {
            size_t off = (size_t)n*Ncols + g*H + j;
            float4 a = *(const float4*)&buf[off];
            for (int sp = 1; sp < nspl; ++sp) {
                float4 p = *(const float4*)&buf[(size_t)sp*psz + off];
                a.x += p.x; a.y += p.y; a.z += p.z; a.w += p.w;
            }
            float4 bi = *(const float4*)&b_ih[g*H + j];
            float4 bh = *(const float4*)&b_hh[g*H + j];
            a.x += bi.x + bh.x; a.y += bi.y + bh.y;
            a.z += bi.z + bh.z; a.w += bi.w + bh.w;
            gs[g] = a;
        }
        size_t idx = (size_t)n*H + j;
        float4 cv = *(const float4*)&cst[idx];
        float hn[4], cn[4];
        const float* fi = (const float*)&gs[0];
        const float* ff = (const float*)&gs[1];
        const float* fg = (const float*)&gs[2];
        const float* fo = (const float*)&gs[3];
        const float* pc = (const float*)&cv;
        #pragma unroll
        for (int c = 0; c < 4; ++c) {
            float nc = sigf(ff[c])*pc[c] + sigf(fi[c])*tanhf(fg[c]);
            cn[c] = nc;
            hn[c] = sigf(fo[c])*tanhf(nc);
        }
        *(float4*)&cst[idx] = *(float4*)cn;
        *(float4*)&hst[idx] = *(float4*)hn;
    }
}

// ---- attention + cell3 + output head: one CTA per n (cta < 256) ----
__device__ void attn_phase(const int* __restrict__ seqlen,
                           const float* __restrict__ keys,
                           const float* __restrict__ values,
                           const float* __restrict__ b_ih3,
                           const float* __restrict__ b_hh3,
                           const float* __restrict__ lin_b,
                           const float* __restrict__ charW,
                           const float* __restrict__ charb,
                           float* __restrict__ preds,
                           float* __restrict__ attns,
                           int t, float* s_mem)
{
    float* h3s  = s_mem;          // 128
    float* es   = s_mem + 128;    // 1000
    float* ctxp = s_mem + 1128;   // 8*128
    float* ctxv = s_mem + 2152;   // 128
    float* mids = s_mem + 2280;   // 128
    float* red  = s_mem + 2408;   // 8

    const int n = blockIdx.x;
    const int tid = threadIdx.x;
    const int w = tid >> 5, l = tid & 31;

    if (tid < KD) {   // cell3 from 8 LSTM3 partials (Ncols = 512)
        int j = tid;
        float g4[4];
        #pragma unroll
        for (int g = 0; g < 4; ++g) {
            size_t off = (size_t)n*512 + g*KD + j;
            float a = gp3[off];
            #pragma unroll
            for (int sp = 1; sp < 8; ++sp) a += gp3[(size_t)sp*PSZ3 + off];
            g4[g] = a + b_ih3[g*KD + j] + b_hh3[g*KD + j];
        }
        size_t idx = (size_t)n*KD + j;
        float cn = sigf(g4[1])*g_c3[idx] + sigf(g4[0])*tanhf(g4[2]);
        g_c3[idx] = cn;
        float hv = sigf(g4[3])*tanhf(cn);
        g_h3[idx] = hv;
        h3s[j] = hv;
    }
    int len = seqlen[n];
    if (len < 1) len = 1; if (len > TT) len = TT;
    __syncthreads();

    {   // energies: 64 taus per CTA-iteration (x2 MLP unroll)
        int g = l >> 3, kq = l & 7;
        const float4* h34 = (const float4*)h3s;
        float4 hv[4];
        #pragma unroll
        for (int q = 0; q < 4; ++q) hv[q] = h34[kq + (q<<3)];
        int nIt = (len + 63) >> 6;
        for (int it = 0; it < nIt; ++it) {
            int tauA = (it << 6) + (w << 2) + g;
            int tauB = tauA + 32;
            bool vA = tauA < len, vB = tauB < len;
            float4 ka[4], kb[4];
            if (vA) {
                const float4* kp = (const float4*)(keys + ((size_t)tauA*NB + n)*KD);
                #pragma unroll
                for (int q = 0; q < 4; ++q) ka[q] = kp[kq + (q<<3)];
            }
            if (vB) {
                const float4* kp = (const float4*)(keys + ((size_t)tauB*NB + n)*KD);
                #pragma unroll
                for (int q = 0; q < 4; ++q) kb[q] = kp[kq + (q<<3)];
            }
            float pA = 0.f, pB = 0.f;
            if (vA) {
                #pragma unroll
                for (int q = 0; q < 4; ++q)
                    pA += ka[q].x*hv[q].x + ka[q].y*hv[q].y + ka[q].z*hv[q].z + ka[q].w*hv[q].w;
            }
            if (vB) {
                #pragma unroll
                for (int q = 0; q < 4; ++q)
                    pB += kb[q].x*hv[q].x + kb[q].y*hv[q].y + kb[q].z*hv[q].z + kb[q].w*hv[q].w;
            }
            pA += __shfl_xor_sync(0xffffffffu, pA, 4);
            pA += __shfl_xor_sync(0xffffffffu, pA, 2);
            pA += __shfl_xor_sync(0xffffffffu, pA, 1);
            pB += __shfl_xor_sync(0xffffffffu, pB, 4);
            pB += __shfl_xor_sync(0xffffffffu, pB, 2);
            pB += __shfl_xor_sync(0xffffffffu, pB, 1);
            if (kq == 0) {
                if (vA) es[tauA] = pA;
                if (vB) es[tauB] = pB;
            }
        }
    }
    __syncthreads();

    float lm = -3.4e38f;
    for (int tau = tid; tau < TT; tau += NTHR) {
        float x = (tau < len) ? es[tau] : -1e9f;
        es[tau] = x;
        lm = fmaxf(lm, x);
    }
    #pragma unroll
    for (int o = 16; o; o >>= 1) lm = fmaxf(lm, __shfl_xor_sync(0xffffffffu, lm, o));
    if (l == 0) red[w] = lm;
    __syncthreads();
    float bm = fmaxf(fmaxf(fmaxf(red[0],red[1]), fmaxf(red[2],red[3])),
                     fmaxf(fmaxf(red[4],red[5]), fmaxf(red[6],red[7])));
    __syncthreads();
    float ls = 0.f;
    for (int tau = tid; tau < TT; tau += NTHR) {
        float p = expf(es[tau] - bm);
        es[tau] = p;
        ls += p;
    }
    #pragma unroll
    for (int o = 16; o; o >>= 1) ls += __shfl_xor_sync(0xffffffffu, ls, o);
    if (l == 0) red[w] = ls;
    __syncthreads();
    float inv = 1.f/(red[0]+red[1]+red[2]+red[3]+red[4]+red[5]+red[6]+red[7]);
    float* arow = attns + ((size_t)t*NB + n)*TT;
    for (int tau = tid; tau < TT; tau += NTHR) {
        float a = es[tau] * inv;
        es[tau] = a;
        arow[tau] = a;
    }
    __syncthreads();

    {   // ctx = attn @ values (x2 MLP unroll)
        float4 acc = make_float4(0.f, 0.f, 0.f, 0.f);
        for (int tau = w; tau < len; tau += 16) {
            int tau2 = tau + 8;
            float a0 = es[tau];
            float4 v0 = ((const float4*)(values + ((size_t)tau*NB + n)*VD))[l];
            float a1 = 0.f; float4 v1 = make_float4(0.f,0.f,0.f,0.f);
            if (tau2 < len) {
                a1 = es[tau2];
                v1 = ((const float4*)(values + ((size_t)tau2*NB + n)*VD))[l];
            }
            acc.x += a0*v0.x + a1*v1.x;
            acc.y += a0*v0.y + a1*v1.y;
            acc.z += a0*v0.z + a1*v1.z;
            acc.w += a0*v0.w + a1*v1.w;
        }
        *(float4*)&ctxp[w*VD + (l<<2)] = acc;
    }
    __syncthreads();
    if (tid < VD) {
        float s = 0.f;
        #pragma unroll
        for (int ww = 0; ww < 8; ++ww) s += ctxp[ww*VD + tid];
        g_ctx[n*VD + tid] = s;
        ctxv[tid] = s;
    }
    __syncthreads();

    if (tid < KD) {
        float m = lin_b[tid];
        #pragma unroll 4
        for (int k = 0; k < KD; ++k) m += h3s[k] * g_linWT[k*KD + tid];
        #pragma unroll 4
        for (int k = 0; k < VD; ++k) m += ctxv[k] * g_linWT[(KD+k)*KD + tid];
        mids[tid] = m;
    }
    __syncthreads();
    if (tid < VOC) {
        float p = charb[tid];
        #pragma unroll 4
        for (int k = 0; k < KD; ++k) p += mids[k] * charW[tid*KD + k];
        preds[((size_t)n*ML + t)*VOC + tid] = p;
    }
}

// ---- single persistent kernel ----
__global__ void __launch_bounds__(NTHR, 2)
decoder_persistent(const float* __restrict__ keys, const float* __restrict__ values,
                   const int* __restrict__ seqlen, const int* __restrict__ text,
                   const float* __restrict__ embW,
                   const float* __restrict__ w_ih1, const float* __restrict__ w_hh1,
                   const float* __restrict__ b_ih1, const float* __restrict__ b_hh1,
                   const float* __restrict__ w_ih2, const float* __restrict__ w_hh2,
                   const float* __restrict__ b_ih2, const float* __restrict__ b_hh2,
                   const float* __restrict__ w_ih3, const float* __restrict__ w_hh3,
                   const float* __restrict__ b_ih3, const float* __restrict__ b_hh3,
                   const float* __restrict__ lin_W, const float* __restrict__ lin_b,
                   const float* __restrict__ char_W, const float* __restrict__ char_b,
                   float* __restrict__ preds, float* __restrict__ attns)
{
    __shared__ __align__(16) float s_mem[32*132 + 32*68];   // 25.6 KB
    const int cta = blockIdx.x;
    const int gid = cta*NTHR + threadIdx.x;
    const int GS = NCTA*NTHR;

    for (int i = gid; i < ML*NB*(ED/4); i += GS) {
        int e4 = i & 63; int rem = i >> 6; int n = rem & 255; int tt = rem >> 8;
        int ch = text[n*ML + tt];
        ((float4*)g_embs)[i] = ((const float4*)embW)[ch*(ED/4) + e4];
    }
    for (int i = gid; i < NB*HD; i += GS) {
        g_h1[i] = 0.f; g_c1[i] = 0.f; g_h2[i] = 0.f; g_c2[i] = 0.f;
    }
    for (int i = gid; i < NB*KD; i += GS) { g_h3[i] = 0.f; g_c3[i] = 0.f; }
    for (int i = gid; i < NB*VD; i += GS) g_ctx[i] = values[(size_t)(TT-1)*NB*VD + i];
    for (int i = gid; i < (KD+VD)*KD; i += GS) {
        int k = i >> 7, j = i & 127;
        g_linWT[i] = lin_W[j*(KD+VD) + k];
    }
    gridbar();

    for (int t = 0; t < ML; ++t) {
        {   // LSTM1: K = 256+128+512 = 896, 64 tiles x spl4 = 256 CTAs
            Seg segs[3] = {
                { g_embs + (size_t)t*NB*ED, ED, w_ih1,      ED+VD, ED },
                { g_ctx,                    VD, w_ih1 + ED, ED+VD, VD },
                { g_h1,                     HD, w_hh1,      HD,    HD } };
            gemm_part(segs, 3, 2048, ED+VD+HD, gp1, PSZ1, 4, s_mem);
        }
        gridbar();
        cell_sum(HD, gp1, 4, PSZ1, b_ih1, b_hh1, g_h1, g_c1);
        gridbar();
        {   // LSTM2: K = 1024, 64 tiles x spl4 = 256 CTAs
            Seg segs[2] = {
                { g_h1, HD, w_ih2, HD, HD },
                { g_h2, HD, w_hh2, HD, HD } };
            gemm_part(segs, 2, 2048, 2*HD, gp2, PSZ1, 4, s_mem);
        }
        gridbar();
        cell_sum(HD, gp2, 4, PSZ1, b_ih2, b_hh2, g_h2, g_c2);
        gridbar();
        {   // LSTM3: K = 640, 16 tiles x spl8 = 128 CTAs
            Seg segs[2] = {
                { g_h2, HD, w_ih3, HD, HD },
                { g_h3, KD, w_hh3, KD, KD } };
            gemm_part(segs, 2, 512, HD+KD, gp3, PSZ3, 8, s_mem);
        }
        gridbar();
        if (cta < NB)
            attn_phase(seqlen, keys, values, b_ih3, b_hh3, lin_b, char_W, char_b,
                       preds, attns, t, s_mem);
        gridbar();
    }
}

// ---- host ----
extern "C" void kernel_launch(void* const* d_in, const int* in_sizes, int n_in,
                              void* d_out, int out_size) {
    (void)in_sizes; (void)n_in; (void)out_size;
    const float* keys   = (const float*)d_in[0];
    const float* values = (const float*)d_in[1];
    const int*   seqlen = (const int*)  d_in[2];
    const int*   text   = (const int*)  d_in[3];
    const float* embW   = (const float*)d_in[4];
    const float* w_ih1  = (const float*)d_in[5];
    const float* w_hh1  = (const float*)d_in[6];
    const float* b_ih1  = (const float*)d_in[7];
    const float* b_hh1  = (const float*)d_in[8];
    const float* w_ih2  = (const float*)d_in[9];
    const float* w_hh2  = (const float*)d_in[10];
    const float* b_ih2  = (const float*)d_in[11];
    const float* b_hh2  = (const float*)d_in[12];
    const float* w_ih3  = (const float*)d_in[13];
    const float* w_hh3  = (const float*)d_in[14];
    const float* b_ih3  = (const float*)d_in[15];
    const float* b_hh3  = (const float*)d_in[16];
    const float* lin_W  = (const float*)d_in[17];
    const float* lin_b  = (const float*)d_in[18];
    const float* char_W = (const float*)d_in[19];
    const float* char_b = (const float*)d_in[20];

    float* preds = (float*)d_out;
    float* attns = preds + (size_t)NB*ML*VOC;

    decoder_persistent<<<NCTA, NTHR>>>(
        keys, values, seqlen, text, embW,
        w_ih1, w_hh1, b_ih1, b_hh1,
        w_ih2, w_hh2, b_ih2, b_hh2,
        w_ih3, w_hh3, b_ih3, b_hh3,
        lin_W, lin_b, char_W, char_b,
        preds, attns);
}

// round 13
// speedup vs baseline: 1.0082x; 1.0082x over previous
#include <cuda_runtime.h>
#include <math.h>

#define NB 256
#define TT 1000
#define KD 128
#define VD 128
#define ED 256
#define HD 512
#define ML 250
#define VOC 30
#define NCTA 296
#define NTHR 256
#define PSZ1 ((size_t)NB*2048)
#define PSZ3 ((size_t)NB*512)

typedef unsigned long long ull;

__device__ __align__(16) float g_embs[(size_t)ML*NB*ED];
__device__ __align__(16) float g_h1[NB*HD], g_c1[NB*HD];
__device__ __align__(16) float g_h2[NB*HD], g_c2[NB*HD];
__device__ __align__(16) float g_h3[NB*KD], g_c3[NB*KD];
__device__ __align__(16) float g_ctx[NB*VD];
__device__ __align__(16) float g_linWT[(KD+VD)*KD];
__device__ __align__(16) float gp1[4*PSZ1];
__device__ __align__(16) float gp2[4*PSZ1];
__device__ __align__(16) float gp3[8*PSZ3];
__device__ unsigned g_grp[8*32];
__device__ unsigned g_root, g_gen;

// ---- two-level grid barrier: 8 groups of 37 + root ----
__device__ __forceinline__ void gridbar() {
    __syncthreads();
    if (threadIdx.x == 0) {
        unsigned snap = *(volatile unsigned*)&g_gen;
        __threadfence();
        unsigned a = atomicAdd(&g_grp[(blockIdx.x & 7) * 32], 1u);
        if (a == 36u) {
            unsigned r = atomicAdd(&g_root, 1u);
            if (r == 7u) {
                #pragma unroll
                for (int i = 0; i < 8; ++i) g_grp[i*32] = 0u;
                g_root = 0u;
                __threadfence();
                atomicAdd(&g_gen, 1u);
            }
        }
        while (*(volatile unsigned*)&g_gen == snap) __nanosleep(32);
        __threadfence();
    }
    __syncthreads();
}

__device__ __forceinline__ ull packdup(float x) {
    ull r;
    asm("mov.b64 %0, {%1, %1};" : "=l"(r) : "r"(__float_as_uint(x)));
    return r;
}
__device__ __forceinline__ void ffma2(ull& d, ull a, ull b) {
    asm("fma.rn.f32x2 %0, %1, %2, %0;" : "+l"(d) : "l"(a), "l"(b));
}
__device__ __forceinline__ float2 unpack2(ull v) {
    unsigned lo, hi;
    asm("mov.b64 {%0, %1}, %2;" : "=r"(lo), "=r"(hi) : "l"(v));
    float2 f; f.x = __uint_as_float(lo); f.y = __uint_as_float(hi);
    return f;
}
__device__ __forceinline__ float sigf(float x) { return 1.f/(1.f + expf(-x)); }

struct Seg { const float* A; int lda; const float* W; int ldw; int K; };

__device__ __forceinline__ void resolve(const Seg* segs, int nseg, int kb,
                                        const float*& Ap, int& la,
                                        const float*& Wp, int& lw) {
    Ap = segs[0].A; la = segs[0].lda; Wp = segs[0].W; lw = segs[0].ldw;
    int base = 0;
    for (int q = 0; q < nseg; ++q) {
        if (kb >= base && kb < base + segs[q].K) {
            Ap = segs[q].A + (kb - base); la = segs[q].lda;
            Wp = segs[q].W + (kb - base); lw = segs[q].ldw;
        }
        base += segs[q].K;
    }
}

// ---- split-K GEMM: BM=128, BN=64, per-thread 8x4, FFMA2, reg double-buffer ----
__device__ void gemm_part(const Seg* segs, int nseg, int Ncols, int Ktot,
                          float* dstbase, size_t psz, int spl, float* s_mem)
{
    const int nt = Ncols >> 6;          // tiles along N (BN=64)
    const int tiles = 2*nt;             // M=256 -> 2 m-tiles
    const int local = blockIdx.x;
    if (local >= tiles*spl) return;
    const int s  = local / tiles;
    const int rem = local - s*tiles;
    const int m0 = (rem / nt) * 128;
    const int j0 = (rem % nt) * 64;
    const int nbt = Ktot >> 5;
    const int b0 = (nbt*s)/spl, b1 = (nbt*(s+1))/spl;

    float* As = s_mem;                  // [32][132]
    float* Ws = s_mem + 32*132;         // [32][68]
    const int tid = threadIdx.x;
    const int tx = tid & 15, ty = tid >> 4;

    ull acc[8][2];
    #pragma unroll
    for (int i = 0; i < 8; ++i) { acc[i][0] = 0ull; acc[i][1] = 0ull; }

    float4 pa[4], pw[2];

    if (b0 < b1) {      // prefetch first block
        const float* Ap; int la; const float* Wp; int lw;
        resolve(segs, nseg, b0 << 5, Ap, la, Wp, lw);
        #pragma unroll
        for (int it = 0; it < 4; ++it) {
            int q = tid + (it << 8); int m = q >> 3, kq = q & 7;
            pa[it] = *(const float4*)(Ap + (size_t)(m0+m)*la + (kq << 2));
        }
        #pragma unroll
        for (int it = 0; it < 2; ++it) {
            int q = tid + (it << 8); int j = q >> 3, kq = q & 7;
            pw[it] = *(const float4*)(Wp + (size_t)(j0+j)*lw + (kq << 2));
        }
    }

    for (int b = b0; b < b1; ++b) {
        __syncthreads();
        #pragma unroll
        for (int it = 0; it < 4; ++it) {     // A tile -> smem (transposed)
            int q = tid + (it << 8); int m = q >> 3, kq = q & 7;
            As[(kq*4+0)*132 + m] = pa[it].x;
            As[(kq*4+1)*132 + m] = pa[it].y;
            As[(kq*4+2)*132 + m] = pa[it].z;
            As[(kq*4+3)*132 + m] = pa[it].w;
        }
        #pragma unroll
        for (int it = 0; it < 2; ++it) {     // W tile -> smem (transposed)
            int q = tid + (it << 8); int j = q >> 3, kq = q & 7;
            Ws[(kq*4+0)*68 + j] = pw[it].x;
            Ws[(kq*4+1)*68 + j] = pw[it].y;
            Ws[(kq*4+2)*68 + j] = pw[it].z;
            Ws[(kq*4+3)*68 + j] = pw[it].w;
        }
        __syncthreads();

        if (b + 1 < b1) {   // prefetch next block during compute
            const float* Ap; int la; const float* Wp; int lw;
            resolve(segs, nseg, (b+1) << 5, Ap, la, Wp, lw);
            #pragma unroll
            for (int it = 0; it < 4; ++it) {
                int q = tid + (it << 8); int m = q >> 3, kq = q & 7;
                pa[it] = *(const float4*)(Ap + (size_t)(m0+m)*la + (kq << 2));
            }
            #pragma unroll
            for (int it = 0; it < 2; ++it) {
                int q = tid + (it << 8); int j = q >> 3, kq = q & 7;
                pw[it] = *(const float4*)(Wp + (size_t)(j0+j)*lw + (kq << 2));
            }
        }

        #pragma unroll 8
        for (int k = 0; k < 32; ++k) {
            float4 a0 = *(const float4*)&As[k*132 + ty*8];
            float4 a1 = *(const float4*)&As[k*132 + ty*8 + 4];
            ull da0 = packdup(a0.x), da1 = packdup(a0.y);
            ull da2 = packdup(a0.z), da3 = packdup(a0.w);
            ull da4 = packdup(a1.x), da5 = packdup(a1.y);
            ull da6 = packdup(a1.z), da7 = packdup(a1.w);
            float4 w0 = *(const float4*)&Ws[k*68 + tx*4];
            const ull* wp = (const ull*)&w0;
            ffma2(acc[0][0], wp[0], da0); ffma2(acc[0][1], wp[1], da0);
            ffma2(acc[1][0], wp[0], da1); ffma2(acc[1][1], wp[1], da1);
            ffma2(acc[2][0], wp[0], da2); ffma2(acc[2][1], wp[1], da2);
            ffma2(acc[3][0], wp[0], da3); ffma2(acc[3][1], wp[1], da3);
            ffma2(acc[4][0], wp[0], da4); ffma2(acc[4][1], wp[1], da4);
            ffma2(acc[5][0], wp[0], da5); ffma2(acc[5][1], wp[1], da5);
            ffma2(acc[6][0], wp[0], da6); ffma2(acc[6][1], wp[1], da6);
            ffma2(acc[7][0], wp[0], da7); ffma2(acc[7][1], wp[1], da7);
        }
    }

    float* dst = dstbase + (size_t)s*psz;
    #pragma unroll
    for (int i = 0; i < 8; ++i) {
        int m = m0 + ty*8 + i;
        int j = j0 + tx*4;
        float2 v0 = unpack2(acc[i][0]), v1 = unpack2(acc[i][1]);
        *(float4*)&dst[(size_t)m*Ncols + j] = make_float4(v0.x, v0.y, v1.x, v1.y);
    }
}

// ---- cell: gates = sum of nspl partials + biases -> LSTM update ----
__device__ void cell_sum(int H, const float* __restrict__ buf, int nspl, size_t psz,
                         const float* __restrict__ b_ih, const float* __restrict__ b_hh,
                         float* __restrict__ hst, float* __restrict__ cst)
{
    const int Ncols = 4*H;
    const int gid = blockIdx.x*NTHR + threadIdx.x;
    const int hq = H >> 2;
    for (int q = gid; q < NB*hq; q += NCTA*NTHR) {
        int n = q / hq, j = (q - n*hq) << 2;
        float4 gs[4];
        #pragma unroll
        for (int g = 0; g < 4; ++g) {
            size_t off = (size_t)n*Ncols + g*H + j;
            float4 a = *(const float4*)&buf[off];
            for (int sp = 1; sp < nspl; ++sp) {
                float4 p = *(const float4*)&buf[(size_t)sp*psz + off];
                a.x += p.x; a.y += p.y; a.z += p.z; a.w += p.w;
            }
            float4 bi = *(const float4*)&b_ih[g*H + j];
            float4 bh = *(const float4*)&b_hh[g*H + j];
            a.x += bi.x + bh.x; a.y += bi.y + bh.y;
            a.z += bi.z + bh.z; a.w += bi.w + bh.w;
            gs[g] = a;
        }
        size_t idx = (size_t)n*H + j;
        float4 cv = *(const float4*)&cst[idx];
        float hn[4], cn[4];
        const float* fi = (const float*)&gs[0];
        const float* ff = (const float*)&gs[1];
        const float* fg = (const float*)&gs[2];
        const float* fo = (const float*)&gs[3];
        const float* pc = (const float*)&cv;
        #pragma unroll
        for (int c = 0; c < 4; ++c) {
            float nc = sigf(ff[c])*pc[c] + sigf(fi[c])*tanhf(fg[c]);
            cn[c] = nc;
            hn[c] = sigf(fo[c])*tanhf(nc);
        }
        *(float4*)&cst[idx] = *(float4*)cn;
        *(float4*)&hst[idx] = *(float4*)hn;
    }
}

// ---- attention + cell3 + output head: one CTA per n (cta < 256) ----
__device__ void attn_phase(const int* __restrict__ seqlen,
                           const float* __restrict__ keys,
                           const float* __restrict__ values,
                           const float* __restrict__ b_ih3,
                           const float* __restrict__ b_hh3,
                           const float* __restrict__ lin_b,
                           const float* __restrict__ charW,
                           const float* __restrict__ charb,
                           float* __restrict__ preds,
                           float* __restrict__ attns,
                           int t, float* s_mem)
{
    float* h3s  = s_mem;          // 128
    float* es   = s_mem + 128;    // 1000
    float* ctxp = s_mem + 1128;   // 8*128
    float* ctxv = s_mem + 2152;   // 128
    float* mids = s_mem + 2280;   // 128
    float* red  = s_mem + 2408;   // 8

    const int n = blockIdx.x;
    const int tid = threadIdx.x;
    const int w = tid >> 5, l = tid & 31;

    if (tid < KD) {   // cell3 from 8 LSTM3 partials (Ncols = 512)
        int j = tid;
        float g4[4];
        #pragma unroll
        for (int g = 0; g < 4; ++g) {
            size_t off = (size_t)n*512 + g*KD + j;
            float a = gp3[off];
            #pragma unroll
            for (int sp = 1; sp < 8; ++sp) a += gp3[(size_t)sp*PSZ3 + off];
            g4[g] = a + b_ih3[g*KD + j] + b_hh3[g*KD + j];
        }
        size_t idx = (size_t)n*KD + j;
        float cn = sigf(g4[1])*g_c3[idx] + sigf(g4[0])*tanhf(g4[2]);
        g_c3[idx] = cn;
        float hv = sigf(g4[3])*tanhf(cn);
        g_h3[idx] = hv;
        h3s[j] = hv;
    }
    int len = seqlen[n];
    if (len < 1) len = 1; if (len > TT) len = TT;
    __syncthreads();

    {   // energies: 64 taus per CTA-iteration (x2 MLP unroll)
        int g = l >> 3, kq = l & 7;
        const float4* h34 = (const float4*)h3s;
        float4 hv[4];
        #pragma unroll
        for (int q = 0; q < 4; ++q) hv[q] = h34[kq + (q<<3)];
        int nIt = (len + 63) >> 6;
        for (int it = 0; it < nIt; ++it) {
            int tauA = (it << 6) + (w << 2) + g;
            int tauB = tauA + 32;
            bool vA = tauA < len, vB = tauB < len;
            float4 ka[4], kb[4];
            if (vA) {
                const float4* kp = (const float4*)(keys + ((size_t)tauA*NB + n)*KD);
                #pragma unroll
                for (int q = 0; q < 4; ++q) ka[q] = kp[kq + (q<<3)];
            }
            if (vB) {
                const float4* kp = (const float4*)(keys + ((size_t)tauB*NB + n)*KD);
                #pragma unroll
                for (int q = 0; q < 4; ++q) kb[q] = kp[kq + (q<<3)];
            }
            float pA = 0.f, pB = 0.f;
            if (vA) {
                #pragma unroll
                for (int q = 0; q < 4; ++q)
                    pA += ka[q].x*hv[q].x + ka[q].y*hv[q].y + ka[q].z*hv[q].z + ka[q].w*hv[q].w;
            }
            if (vB) {
                #pragma unroll
                for (int q = 0; q < 4; ++q)
                    pB += kb[q].x*hv[q].x + kb[q].y*hv[q].y + kb[q].z*hv[q].z + kb[q].w*hv[q].w;
            }
            pA += __shfl_xor_sync(0xffffffffu, pA, 4);
            pA += __shfl_xor_sync(0xffffffffu, pA, 2);
            pA += __shfl_xor_sync(0xffffffffu, pA, 1);
            pB += __shfl_xor_sync(0xffffffffu, pB, 4);
            pB += __shfl_xor_sync(0xffffffffu, pB, 2);
            pB += __shfl_xor_sync(0xffffffffu, pB, 1);
            if (kq == 0) {
                if (vA) es[tauA] = pA;
                if (vB) es[tauB] = pB;
            }
        }
    }
    __syncthreads();

    float lm = -3.4e38f;
    for (int tau = tid; tau < TT; tau += NTHR) {
        float x = (tau < len) ? es[tau] : -1e9f;
        es[tau] = x;
        lm = fmaxf(lm, x);
    }
    #pragma unroll
    for (int o = 16; o; o >>= 1) lm = fmaxf(lm, __shfl_xor_sync(0xffffffffu, lm, o));
    if (l == 0) red[w] = lm;
    __syncthreads();
    float bm = fmaxf(fmaxf(fmaxf(red[0],red[1]), fmaxf(red[2],red[3])),
                     fmaxf(fmaxf(red[4],red[5]), fmaxf(red[6],red[7])));
    __syncthreads();
    float ls = 0.f;
    for (int tau = tid; tau < TT; tau += NTHR) {
        float p = expf(es[tau] - bm);
        es[tau] = p;
        ls += p;
    }
    #pragma unroll
    for (int o = 16; o; o >>= 1) ls += __shfl_xor_sync(0xffffffffu, ls, o);
    if (l == 0) red[w] = ls;
    __syncthreads();
    float inv = 1.f/(red[0]+red[1]+red[2]+red[3]+red[4]+red[5]+red[6]+red[7]);
    float* arow = attns + ((size_t)t*NB + n)*TT;
    for (int tau = tid; tau < TT; tau += NTHR) {
        float a = es[tau] * inv;
        es[tau] = a;
        arow[tau] = a;
    }
    __syncthreads();

    {   // ctx = attn @ values (x2 MLP unroll)
        float4 acc = make_float4(0.f, 0.f, 0.f, 0.f);
        for (int tau = w; tau < len; tau += 16) {
            int tau2 = tau + 8;
            float a0 = es[tau];
            float4 v0 = ((const float4*)(values + ((size_t)tau*NB + n)*VD))[l];
            float a1 = 0.f; float4 v1 = make_float4(0.f,0.f,0.f,0.f);
            if (tau2 < len) {
                a1 = es[tau2];
                v1 = ((const float4*)(values + ((size_t)tau2*NB + n)*VD))[l];
            }
            acc.x += a0*v0.x + a1*v1.x;
            acc.y += a0*v0.y + a1*v1.y;
            acc.z += a0*v0.z + a1*v1.z;
            acc.w += a0*v0.w + a1*v1.w;
        }
        *(float4*)&ctxp[w*VD + (l<<2)] = acc;
    }
    __syncthreads();
    if (tid < VD) {
        float s = 0.f;
        #pragma unroll
        for (int ww = 0; ww < 8; ++ww) s += ctxp[ww*VD + tid];
        g_ctx[n*VD + tid] = s;
        ctxv[tid] = s;
    }
    __syncthreads();

    if (tid < KD) {
        float m = lin_b[tid];
        #pragma unroll 4
        for (int k = 0; k < KD; ++k) m += h3s[k] * g_linWT[k*KD + tid];
        #pragma unroll 4
        for (int k = 0; k < VD; ++k) m += ctxv[k] * g_linWT[(KD+k)*KD + tid];
        mids[tid] = m;
    }
    __syncthreads();
    if (tid < VOC) {
        float p = charb[tid];
        #pragma unroll 4
        for (int k = 0; k < KD; ++k) p += mids[k] * charW[tid*KD + k];
        preds[((size_t)n*ML + t)*VOC + tid] = p;
    }
}

// ---- single persistent kernel ----
__global__ void __launch_bounds__(NTHR, 2)
decoder_persistent(const float* __restrict__ keys, const float* __restrict__ values,
                   const int* __restrict__ seqlen, const int* __restrict__ text,
                   const float* __restrict__ embW,
                   const float* __restrict__ w_ih1, const float* __restrict__ w_hh1,
                   const float* __restrict__ b_ih1, const float* __restrict__ b_hh1,
                   const float* __restrict__ w_ih2, const float* __restrict__ w_hh2,
                   const float* __restrict__ b_ih2, const float* __restrict__ b_hh2,
                   const float* __restrict__ w_ih3, const float* __restrict__ w_hh3,
                   const float* __restrict__ b_ih3, const float* __restrict__ b_hh3,
                   const float* __restrict__ lin_W, const float* __restrict__ lin_b,
                   const float* __restrict__ char_W, const float* __restrict__ char_b,
                   float* __restrict__ preds, float* __restrict__ attns)
{
    __shared__ __align__(16) float s_mem[32*132 + 32*68];   // 25.6 KB
    const int cta = blockIdx.x;
    const int gid = cta*NTHR + threadIdx.x;
    const int GS = NCTA*NTHR;

    for (int i = gid; i < ML*NB*(ED/4); i += GS) {
        int e4 = i & 63; int rem = i >> 6; int n = rem & 255; int tt = rem >> 8;
        int ch = text[n*ML + tt];
        ((float4*)g_embs)[i] = ((const float4*)embW)[ch*(ED/4) + e4];
    }
    for (int i = gid; i < NB*HD; i += GS) {
        g_h1[i] = 0.f; g_c1[i] = 0.f; g_h2[i] = 0.f; g_c2[i] = 0.f;
    }
    for (int i = gid; i < NB*KD; i += GS) { g_h3[i] = 0.f; g_c3[i] = 0.f; }
    for (int i = gid; i < NB*VD; i += GS) g_ctx[i] = values[(size_t)(TT-1)*NB*VD + i];
    for (int i = gid; i < (KD+VD)*KD; i += GS) {
        int k = i >> 7, j = i & 127;
        g_linWT[i] = lin_W[j*(KD+VD) + k];
    }
    gridbar();

    for (int t = 0; t < ML; ++t) {
        {   // LSTM1: K = 256+128+512 = 896, 64 tiles x spl4 = 256 CTAs
            Seg segs[3] = {
                { g_embs + (size_t)t*NB*ED, ED, w_ih1,      ED+VD, ED },
                { g_ctx,                    VD, w_ih1 + ED, ED+VD, VD },
                { g_h1,                     HD, w_hh1,      HD,    HD } };
            gemm_part(segs, 3, 2048, ED+VD+HD, gp1, PSZ1, 4, s_mem);
        }
        gridbar();
        cell_sum(HD, gp1, 4, PSZ1, b_ih1, b_hh1, g_h1, g_c1);
        gridbar();
        {   // LSTM2: K = 1024, 64 tiles x spl4 = 256 CTAs
            Seg segs[2] = {
                { g_h1, HD, w_ih2, HD, HD },
                { g_h2, HD, w_hh2, HD, HD } };
            gemm_part(segs, 2, 2048, 2*HD, gp2, PSZ1, 4, s_mem);
        }
        gridbar();
        cell_sum(HD, gp2, 4, PSZ1, b_ih2, b_hh2, g_h2, g_c2);
        gridbar();
        {   // LSTM3: K = 640, 16 tiles x spl8 = 128 CTAs
            Seg segs[2] = {
                { g_h2, HD, w_ih3, HD, HD },
                { g_h3, KD, w_hh3, KD, KD } };
            gemm_part(segs, 2, 512, HD+KD, gp3, PSZ3, 8, s_mem);
        }
        gridbar();
        if (cta < NB)
            attn_phase(seqlen, keys, values, b_ih3, b_hh3, lin_b, char_W, char_b,
                       preds, attns, t, s_mem);
        gridbar();
    }
}

// ---- host ----
extern "C" void kernel_launch(void* const* d_in, const int* in_sizes, int n_in,
                              void* d_out, int out_size) {
    (void)in_sizes; (void)n_in; (void)out_size;
    const float* keys   = (const float*)d_in[0];
    const float* values = (const float*)d_in[1];
    const int*   seqlen = (const int*)  d_in[2];
    const int*   text   = (const int*)  d_in[3];
    const float* embW   = (const float*)d_in[4];
    const float* w_ih1  = (const float*)d_in[5];
    const float* w_hh1  = (const float*)d_in[6];
    const float* b_ih1  = (const float*)d_in[7];
    const float* b_hh1  = (const float*)d_in[8];
    const float* w_ih2  = (const float*)d_in[9];
    const float* w_hh2  = (const float*)d_in[10];
    const float* b_ih2  = (const float*)d_in[11];
    const float* b_hh2  = (const float*)d_in[12];
    const float* w_ih3  = (const float*)d_in[13];
    const float* w_hh3  = (const float*)d_in[14];
    const float* b_ih3  = (const float*)d_in[15];
    const float* b_hh3  = (const float*)d_in[16];
    const float* lin_W  = (const float*)d_in[17];
    const float* lin_b  = (const float*)d_in[18];
    const float* char_W = (const float*)d_in[19];
    const float* char_b = (const float*)d_in[20];

    float* preds = (float*)d_out;
    float* attns = preds + (size_t)NB*ML*VOC;

    decoder_persistent<<<NCTA, NTHR>>>(
        keys, values, seqlen, text, embW,
        w_ih1, w_hh1, b_ih1, b_hh1,
        w_ih2, w_hh2, b_ih2, b_hh2,
        w_ih3, w_hh3, b_ih3, b_hh3,
        lin_W, lin_b, char_W, char_b,
        preds, attns);
}

// round 15
// speedup vs baseline: 1.8214x; 1.8066x over previous
#include <cuda_runtime.h>
#include <cuda_bf16.h>
#include <math.h>

#define NB 256
#define TT 1000
#define KD 128
#define VD 128
#define ED 256
#define HD 512
#define ML 250
#define VOC 30
#define NCTA 256
#define NTHR 256
#define K1 896
#define K2 1024
#define K3 640
#define PSZ1 ((size_t)NB*2048)
#define PSZ3 ((size_t)NB*512)

typedef unsigned u32;
typedef __nv_bfloat16 bf16;

__device__ __align__(16) bf16 g_ehi[(size_t)ML*NB*ED], g_elo[(size_t)ML*NB*ED];
__device__ __align__(16) bf16 g_h1hi[NB*HD], g_h1lo[NB*HD];
__device__ __align__(16) bf16 g_h2hi[NB*HD], g_h2lo[NB*HD];
__device__ __align__(16) bf16 g_h3hi[NB*KD], g_h3lo[NB*KD];
__device__ __align__(16) bf16 g_ctxhi[NB*VD], g_ctxlo[NB*VD];
__device__ __align__(16) float g_c1[NB*HD], g_c2[NB*HD], g_c3[NB*KD];
__device__ __align__(16) float g_h3f[NB*KD];
__device__ __align__(16) bf16 g_w1hi[2048*K1], g_w1lo[2048*K1];
__device__ __align__(16) bf16 g_w2hi[2048*K2], g_w2lo[2048*K2];
__device__ __align__(16) bf16 g_w3hi[512*K3],  g_w3lo[512*K3];
__device__ __align__(16) float g_linWT[(KD+VD)*KD];
__device__ __align__(16) float gp1[4*PSZ1];
__device__ __align__(16) float gp2[4*PSZ1];
__device__ __align__(16) float gp3[8*PSZ3];
__device__ unsigned g_grp[8*32];
__device__ unsigned g_root, g_gen;

__device__ __forceinline__ void gridbar() {
    __syncthreads();
    if (threadIdx.x == 0) {
        unsigned snap = *(volatile unsigned*)&g_gen;
        __threadfence();
        unsigned a = atomicAdd(&g_grp[(blockIdx.x & 7) * 32], 1u);
        if (a == 31u) {
            unsigned r = atomicAdd(&g_root, 1u);
            if (r == 7u) {
                #pragma unroll
                for (int i = 0; i < 8; ++i) g_grp[i*32] = 0u;
                g_root = 0u;
                __threadfence();
                atomicAdd(&g_gen, 1u);
            }
        }
        while (*(volatile unsigned*)&g_gen == snap) __nanosleep(32);
        __threadfence();
    }
    __syncthreads();
}

__device__ __forceinline__ float sigf(float x) { return 1.f/(1.f + expf(-x)); }
__device__ __forceinline__ u32 s2u(const void* p) {
    u32 a;
    asm("{ .reg .u64 t; cvta.to.shared.u64 t, %1; cvt.u32.u64 %0, t; }" : "=r"(a) : "l"(p));
    return a;
}
__device__ __forceinline__ void cpa16(u32 d, const void* s) {
    asm volatile("cp.async.cg.shared.global [%0], [%1], 16;" :: "r"(d), "l"(s) : "memory");
}
__device__ __forceinline__ void ldsm4(u32* r, u32 a) {
    asm volatile("ldmatrix.sync.aligned.m8n8.x4.shared.b16 {%0,%1,%2,%3},[%4];"
        : "=r"(r[0]), "=r"(r[1]), "=r"(r[2]), "=r"(r[3]) : "r"(a));
}
__device__ __forceinline__ void mmab(float* c, const u32* a, const u32* b) {
    asm volatile("mma.sync.aligned.m16n8k16.row.col.f32.bf16.bf16.f32 "
        "{%0,%1,%2,%3},{%4,%5,%6,%7},{%8,%9},{%0,%1,%2,%3};"
        : "+f"(c[0]), "+f"(c[1]), "+f"(c[2]), "+f"(c[3])
        : "r"(a[0]), "r"(a[1]), "r"(a[2]), "r"(a[3]), "r"(b[0]), "r"(b[1]));
}

struct ASeg { const bf16* hi; const bf16* lo; int lda; int K; };

// ---- HMMA bf16x3 split-K GEMM: CTA 64x128, warp 32x32, k-block 32 ----
__device__ void gemm_part(const ASeg* segs, int nseg,
                          const bf16* __restrict__ Wh, const bf16* __restrict__ Wl,
                          int Ncols, int Ktot, float* dstbase, size_t psz, int spl,
                          u32 SR)
{
    const int ntn = Ncols >> 7;
    const int tiles = 4*ntn;
    const int local = blockIdx.x;
    if (local >= tiles*spl) return;
    const int s  = local / tiles;
    const int rem = local - s*tiles;
    const int m0 = (rem / ntn) * 64;
    const int j0 = (rem % ntn) * 128;
    const int nbt = Ktot >> 5;
    const int b0 = (nbt*s)/spl, b1 = (nbt*(s+1))/spl;
    const int tid = threadIdx.x;
    const int lane = tid & 31, wid = tid >> 5;
    const int wm = (wid & 1) << 5;
    const int wn = (wid >> 1) << 5;

    float acc[2][4][4];
    #pragma unroll
    for (int i = 0; i < 2; ++i)
        #pragma unroll
        for (int j = 0; j < 4; ++j)
            #pragma unroll
            for (int c = 0; c < 4; ++c) acc[i][j][c] = 0.f;

    // per-thread global-load coords
    const int ar = tid >> 2, ac = tid & 3;                 // A: 64 rows x 4 chunks
    const u32 adst = (u32)(ar*64 + ((ac ^ (ar&3)) << 4));
    auto loadb = [&](int b, int st) {
        const u32 SB = SR + (u32)st*24576u;
        const int kb = b << 5;
        const bf16 *ah = segs[0].hi, *al = segs[0].lo; int lda = segs[0].lda, ko = kb;
        int base = 0;
        for (int q = 0; q < nseg; ++q) {
            if (kb >= base && kb < base + segs[q].K) {
                ah = segs[q].hi; al = segs[q].lo; lda = segs[q].lda; ko = kb - base;
            }
            base += segs[q].K;
        }
        const bf16* sa = ah + (size_t)(m0 + ar)*lda + ko + ac*8;
        const bf16* sl = al + (size_t)(m0 + ar)*lda + ko + ac*8;
        cpa16(SB + adst, sa);
        cpa16(SB + 4096u + adst, sl);
        #pragma unroll
        for (int i = 0; i < 2; ++i) {
            int idx = tid + (i << 8);
            int r = idx >> 2, c = idx & 3;                 // W: 128 rows x 4 chunks
            u32 wd = SB + 8192u + (u32)(r*64 + ((c ^ (r&3)) << 4));
            const bf16* swh = Wh + (size_t)(j0 + r)*Ktot + kb + c*8;
            const bf16* swl = Wl + (size_t)(j0 + r)*Ktot + kb + c*8;
            cpa16(wd, swh);
            cpa16(wd + 8192u, swl);
        }
        asm volatile("cp.async.commit_group;" ::: "memory");
    };

    if (b0 < b1) loadb(b0, 0);
    for (int b = b0; b < b1; ++b) {
        const int st = (b - b0) & 1;
        if (b + 1 < b1) {
            loadb(b + 1, st ^ 1);
            asm volatile("cp.async.wait_group 1;" ::: "memory");
        } else {
            asm volatile("cp.async.wait_group 0;" ::: "memory");
        }
        __syncthreads();
        const u32 SB = SR + (u32)st*24576u;
        #pragma unroll
        for (int ks = 0; ks < 2; ++ks) {
            // A frag addresses
            int arl = lane & 15;
            int acc_ = (ks << 1) + (lane >> 4);
            u32 aswz = (u32)((acc_ ^ (arl & 3)) << 4);
            u32 aoff0 = (u32)((wm + arl)*64) + aswz;
            u32 aoff1 = aoff0 + 1024u;
            // W frag addresses
            int wrl = wn + (lane & 7) + ((lane >> 4) << 3);
            int wc = (ks << 1) + ((lane >> 3) & 1);
            u32 wswz = (u32)((wc ^ (lane & 3)) << 4);
            u32 woff0 = (u32)(wrl*64) + wswz;
            u32 woff2 = woff0 + 1024u;
            u32 ah[8], al8[8], wh[8], wl[8];
            ldsm4(ah,     SB + aoff0);        ldsm4(ah + 4,  SB + aoff1);
            ldsm4(al8,    SB + 4096u + aoff0); ldsm4(al8 + 4, SB + 4096u + aoff1);
            ldsm4(wh,     SB + 8192u + woff0); ldsm4(wh + 4,  SB + 8192u + woff2);
            ldsm4(wl,     SB + 16384u + woff0); ldsm4(wl + 4, SB + 16384u + woff2);
            #pragma unroll
            for (int fm = 0; fm < 2; ++fm)
                #pragma unroll
                for (int fn = 0; fn < 4; ++fn) {
                    mmab(acc[fm][fn], ah  + fm*4, wh + fn*2);
                    mmab(acc[fm][fn], al8 + fm*4, wh + fn*2);
                    mmab(acc[fm][fn], ah  + fm*4, wl + fn*2);
                }
        }
        __syncthreads();
    }

    float* dst = dstbase + (size_t)s*psz;
    const int g = lane >> 2, tg = lane & 3;
    #pragma unroll
    for (int fm = 0; fm < 2; ++fm)
        #pragma unroll
        for (int fn = 0; fn < 4; ++fn) {
            int row = m0 + wm + fm*16 + g;
            int col = j0 + wn + fn*8 + tg*2;
            float* c = acc[fm][fn];
            *(float2*)&dst[(size_t)row*Ncols + col] = make_float2(c[0], c[1]);
            *(float2*)&dst[(size_t)(row+8)*Ncols + col] = make_float2(c[2], c[3]);
        }
}

// ---- cell: gates = sum of nspl partials + biases -> LSTM update ----
__device__ void cell_sum(int H, const float* __restrict__ buf, int nspl, size_t psz,
                         const float* __restrict__ b_ih, const float* __restrict__ b_hh,
                         bf16* __restrict__ hhi, bf16* __restrict__ hlo,
                         float* __restrict__ cst)
{
    const int Ncols = 4*H;
    const int gid = blockIdx.x*NTHR + threadIdx.x;
    const int hq = H >> 2;
    for (int q = gid; q < NB*hq; q += NCTA*NTHR) {
        int n = q / hq, j = (q - n*hq) << 2;
        float4 gs[4];
        #pragma unroll
        for (int g = 0; g < 4; ++g) {
            size_t off = (size_t)n*Ncols + g*H + j;
            float4 a = *(const float4*)&buf[off];
            for (int sp = 1; sp < nspl; ++sp) {
                float4 p = *(const float4*)&buf[(size_t)sp*psz + off];
                a.x += p.x; a.y += p.y; a.z += p.z; a.w += p.w;
            }
            float4 bi = *(const float4*)&b_ih[g*H + j];
            float4 bh = *(const float4*)&b_hh[g*H + j];
            a.x += bi.x + bh.x; a.y += bi.y + bh.y;
            a.z += bi.z + bh.z; a.w += bi.w + bh.w;
            gs[g] = a;
        }
        size_t idx = (size_t)n*H + j;
        float4 cv = *(const float4*)&cst[idx];
        float cn[4];
        const float* fi = (const float*)&gs[0];
        const float* ff = (const float*)&gs[1];
        const float* fg = (const float*)&gs[2];
        const float* fo = (const float*)&gs[3];
        const float* pc = (const float*)&cv;
        #pragma unroll
        for (int c = 0; c < 4; ++c) {
            float nc = sigf(ff[c])*pc[c] + sigf(fi[c])*tanhf(fg[c]);
            cn[c] = nc;
            float hv = sigf(fo[c])*tanhf(nc);
            bf16 hb = __float2bfloat16(hv);
            hhi[idx + c] = hb;
            hlo[idx + c] = __float2bfloat16(hv - __bfloat162float(hb));
        }
        *(float4*)&cst[idx] = *(float4*)cn;
    }
}

// ---- attention + cell3 + output head: one CTA per n ----
__device__ void attn_phase(const int* __restrict__ seqlen,
                           const float* __restrict__ keys,
                           const float* __restrict__ values,
                           const float* __restrict__ b_ih3,
                           const float* __restrict__ b_hh3,
                           const float* __restrict__ lin_b,
                           const float* __restrict__ charW,
                           const float* __restrict__ charb,
                           float* __restrict__ preds, float* __restrict__ attns,
                           int t, float* s_mem)
{
    float* h3s  = s_mem;
    float* es   = s_mem + 128;
    float* ctxp = s_mem + 1128;
    float* ctxv = s_mem + 2152;
    float* mids = s_mem + 2280;
    float* red  = s_mem + 2408;
    const int n = blockIdx.x;
    const int tid = threadIdx.x;
    const int w = tid >> 5, l = tid & 31;

    if (tid < KD) {   // cell3 from 8 LSTM3 partials (Ncols = 512)
        int j = tid;
        float g4[4];
        #pragma unroll
        for (int g = 0; g < 4; ++g) {
            size_t off = (size_t)n*512 + g*KD + j;
            float a = gp3[off];
            #pragma unroll
            for (int sp = 1; sp < 8; ++sp) a += gp3[(size_t)sp*PSZ3 + off];
            g4[g] = a + b_ih3[g*KD + j] + b_hh3[g*KD + j];
        }
        size_t idx = (size_t)n*KD + j;
        float cn = sigf(g4[1])*g_c3[idx] + sigf(g4[0])*tanhf(g4[2]);
        g_c3[idx] = cn;
        float hv = sigf(g4[3])*tanhf(cn);
        g_h3f[idx] = hv;
        bf16 hb = __float2bfloat16(hv);
        g_h3hi[idx] = hb;
        g_h3lo[idx] = __float2bfloat16(hv - __bfloat162float(hb));
        h3s[j] = hv;
    }
    int len = seqlen[n];
    if (len < 1) len = 1; if (len > TT) len = TT;
    __syncthreads();

    {
        int g = l >> 3, kq = l & 7;
        const float4* h34 = (const float4*)h3s;
        float4 hv[4];
        #pragma unroll
        for (int q = 0; q < 4; ++q) hv[q] = h34[kq + (q<<3)];
        int nIt = (len + 63) >> 6;
        for (int it = 0; it < nIt; ++it) {
            int tauA = (it << 6) + (w << 2) + g, tauB = tauA + 32;
            bool vA = tauA < len, vB = tauB < len;
            float4 ka[4], kb[4];
            if (vA) { const float4* kp = (const float4*)(keys + ((size_t)tauA*NB + n)*KD);
                #pragma unroll
                for (int q = 0; q < 4; ++q) ka[q] = kp[kq + (q<<3)]; }
            if (vB) { const float4* kp = (const float4*)(keys + ((size_t)tauB*NB + n)*KD);
                #pragma unroll
                for (int q = 0; q < 4; ++q) kb[q] = kp[kq + (q<<3)]; }
            float pA = 0.f, pB = 0.f;
            if (vA) {
                #pragma unroll
                for (int q = 0; q < 4; ++q)
                    pA += ka[q].x*hv[q].x + ka[q].y*hv[q].y + ka[q].z*hv[q].z + ka[q].w*hv[q].w;
            }
            if (vB) {
                #pragma unroll
                for (int q = 0; q < 4; ++q)
                    pB += kb[q].x*hv[q].x + kb[q].y*hv[q].y + kb[q].z*hv[q].z + kb[q].w*hv[q].w;
            }
            pA += __shfl_xor_sync(~0u, pA, 4); pA += __shfl_xor_sync(~0u, pA, 2);
            pA += __shfl_xor_sync(~0u, pA, 1);
            pB += __shfl_xor_sync(~0u, pB, 4); pB += __shfl_xor_sync(~0u, pB, 2);
            pB += __shfl_xor_sync(~0u, pB, 1);
            if (kq == 0) { if (vA) es[tauA] = pA; if (vB) es[tauB] = pB; }
        }
    }
    __syncthreads();
    float lm = -3.4e38f;
    for (int tau = tid; tau < TT; tau += NTHR) {
        float x = (tau < len) ? es[tau] : -1e9f;
        es[tau] = x; lm = fmaxf(lm, x);
    }
    #pragma unroll
    for (int o = 16; o; o >>= 1) lm = fmaxf(lm, __shfl_xor_sync(~0u, lm, o));
    if (l == 0) red[w] = lm;
    __syncthreads();
    float bm = fmaxf(fmaxf(fmaxf(red[0],red[1]), fmaxf(red[2],red[3])),
                     fmaxf(fmaxf(red[4],red[5]), fmaxf(red[6],red[7])));
    __syncthreads();
    float ls = 0.f;
    for (int tau = tid; tau < TT; tau += NTHR) {
        float p = expf(es[tau] - bm); es[tau] = p; ls += p;
    }
    #pragma unroll
    for (int o = 16; o; o >>= 1) ls += __shfl_xor_sync(~0u, ls, o);
    if (l == 0) red[w] = ls;
    __syncthreads();
    float inv = 1.f/(red[0]+red[1]+red[2]+red[3]+red[4]+red[5]+red[6]+red[7]);
    float* arow = attns + ((size_t)t*NB + n)*TT;
    for (int tau = tid; tau < TT; tau += NTHR) {
        float a = es[tau] * inv; es[tau] = a; arow[tau] = a;
    }
    __syncthreads();
    {
        float4 acc = make_float4(0.f,0.f,0.f,0.f);
        for (int tau = w; tau < len; tau += 16) {
            int tau2 = tau + 8;
            float a0 = es[tau];
            float4 v0 = ((const float4*)(values + ((size_t)tau*NB + n)*VD))[l];
            float a1 = 0.f; float4 v1 = make_float4(0.f,0.f,0.f,0.f);
            if (tau2 < len) { a1 = es[tau2];
                v1 = ((const float4*)(values + ((size_t)tau2*NB + n)*VD))[l]; }
            acc.x += a0*v0.x + a1*v1.x; acc.y += a0*v0.y + a1*v1.y;
            acc.z += a0*v0.z + a1*v1.z; acc.w += a0*v0.w + a1*v1.w;
        }
        *(float4*)&ctxp[w*VD + (l<<2)] = acc;
    }
    __syncthreads();
    if (tid < VD) {
        float s = 0.f;
        #pragma unroll
        for (int ww = 0; ww < 8; ++ww) s += ctxp[ww*VD + tid];
        bf16 hb = __float2bfloat16(s);
        g_ctxhi[n*VD + tid] = hb;
        g_ctxlo[n*VD + tid] = __float2bfloat16(s - __bfloat162float(hb));
        ctxv[tid] = s;
    }
    __syncthreads();
    if (tid < KD) {
        float m = lin_b[tid];
        #pragma unroll 4
        for (int k = 0; k < KD; ++k) m += h3s[k] * g_linWT[k*KD + tid];
        #pragma unroll 4
        for (int k = 0; k < VD; ++k) m += ctxv[k] * g_linWT[(KD+k)*KD + tid];
        mids[tid] = m;
    }
    __syncthreads();
    if (tid < VOC) {
        float p = charb[tid];
        #pragma unroll 4
        for (int k = 0; k < KD; ++k) p += mids[k] * charW[tid*KD + k];
        preds[((size_t)n*ML + t)*VOC + tid] = p;
    }
}

__global__ void __launch_bounds__(NTHR, 2)
decoder_persistent(const float* __restrict__ keys, const float* __restrict__ values,
                   const int* __restrict__ seqlen, const int* __restrict__ text,
                   const float* __restrict__ embW,
                   const float* __restrict__ w_ih1, const float* __restrict__ w_hh1,
                   const float* __restrict__ b_ih1, const float* __restrict__ b_hh1,
                   const float* __restrict__ w_ih2, const float* __restrict__ w_hh2,
                   const float* __restrict__ b_ih2, const float* __restrict__ b_hh2,
                   const float* __restrict__ w_ih3, const float* __restrict__ w_hh3,
                   const float* __restrict__ b_ih3, const float* __restrict__ b_hh3,
                   const float* __restrict__ lin_W, const float* __restrict__ lin_b,
                   const float* __restrict__ char_W, const float* __restrict__ char_b,
                   float* __restrict__ preds, float* __restrict__ attns)
{
    __shared__ __align__(1024) unsigned char s_raw[49152];   // 2-stage GEMM / attn scratch
    const int cta = blockIdx.x;
    const int tid = threadIdx.x;
    const int gid = cta*NTHR + tid;
    const int GS = NCTA*NTHR;
    const u32 SR = s2u(s_raw);

    // ---- prep: split emb + weights into bf16 hi/lo, init states ----
    for (int i = gid; i < ML*NB*ED; i += GS) {
        int e = i & 255, rem = i >> 8, n = rem & 255, tt = rem >> 8;
        float v = embW[text[n*ML + tt]*ED + e];
        bf16 hb = __float2bfloat16(v);
        g_ehi[i] = hb; g_elo[i] = __float2bfloat16(v - __bfloat162float(hb));
    }
    for (int i = gid; i < 2048*K1; i += GS) {
        int R = i / K1, k = i - R*K1;
        float v = (k < 384) ? w_ih1[R*384 + k] : w_hh1[R*HD + k - 384];
        bf16 hb = __float2bfloat16(v);
        g_w1hi[i] = hb; g_w1lo[i] = __float2bfloat16(v - __bfloat162float(hb));
    }
    for (int i = gid; i < 2048*K2; i += GS) {
        int R = i >> 10, k = i & 1023;
        float v = (k < 512) ? w_ih2[R*HD + k] : w_hh2[R*HD + k - 512];
        bf16 hb = __float2bfloat16(v);
        g_w2hi[i] = hb; g_w2lo[i] = __float2bfloat16(v - __bfloat162float(hb));
    }
    for (int i = gid; i < 512*K3; i += GS) {
        int R = i / K3, k = i - R*K3;
        float v = (k < 512) ? w_ih3[R*HD + k] : w_hh3[R*KD + k - 512];
        bf16 hb = __float2bfloat16(v);
        g_w3hi[i] = hb; g_w3lo[i] = __float2bfloat16(v - __bfloat162float(hb));
    }
    const bf16 z = __float2bfloat16(0.f);
    for (int i = gid; i < NB*HD; i += GS) {
        g_h1hi[i] = z; g_h1lo[i] = z; g_h2hi[i] = z; g_h2lo[i] = z;
        g_c1[i] = 0.f; g_c2[i] = 0.f;
    }
    for (int i = gid; i < NB*KD; i += GS) {
        g_h3hi[i] = z; g_h3lo[i] = z; g_c3[i] = 0.f; g_h3f[i] = 0.f;
    }
    for (int i = gid; i < NB*VD; i += GS) {
        float v = values[(size_t)(TT-1)*NB*VD + i];
        bf16 hb = __float2bfloat16(v);
        g_ctxhi[i] = hb; g_ctxlo[i] = __float2bfloat16(v - __bfloat162float(hb));
    }
    for (int i = gid; i < (KD+VD)*KD; i += GS) {
        int k = i >> 7, j = i & 127;
        g_linWT[i] = lin_W[j*(KD+VD) + k];
    }
    gridbar();

    for (int t = 0; t < ML; ++t) {
        {   // LSTM1: A = [emb | ctx | h1], K = 896, 64 tiles x spl4 = 256 CTAs
            ASeg s[3] = { { g_ehi + (size_t)t*NB*ED, g_elo + (size_t)t*NB*ED, ED, ED },
                          { g_ctxhi, g_ctxlo, VD, VD },
                          { g_h1hi,  g_h1lo,  HD, HD } };
            gemm_part(s, 3, g_w1hi, g_w1lo, 2048, K1, gp1, PSZ1, 4, SR);
        }
        gridbar();
        cell_sum(HD, gp1, 4, PSZ1, b_ih1, b_hh1, g_h1hi, g_h1lo, g_c1);
        gridbar();
        {   // LSTM2: A = [h1 | h2], K = 1024
            ASeg s[2] = { { g_h1hi, g_h1lo, HD, HD },
                          { g_h2hi, g_h2lo, HD, HD } };
            gemm_part(s, 2, g_w2hi, g_w2lo, 2048, K2, gp2, PSZ1, 4, SR);
        }
        gridbar();
        cell_sum(HD, gp2, 4, PSZ1, b_ih2, b_hh2, g_h2hi, g_h2lo, g_c2);
        gridbar();
        {   // LSTM3: A = [h2 | h3], K = 640, 16 tiles x spl8 = 128 CTAs
            ASeg s[2] = { { g_h2hi, g_h2lo, HD, HD },
                          { g_h3hi, g_h3lo, KD, KD } };
            gemm_part(s, 2, g_w3hi, g_w3lo, 512, K3, gp3, PSZ3, 8, SR);
        }
        gridbar();
        attn_phase(seqlen, keys, values, b_ih3, b_hh3, lin_b, char_W, char_b,
                   preds, attns, t, (float*)s_raw);
        gridbar();
    }
}

extern "C" void kernel_launch(void* const* d_in, const int* in_sizes, int n_in,
                              void* d_out, int out_size) {
    (void)in_sizes; (void)n_in; (void)out_size;
    float* preds = (float*)d_out;
    float* attns = preds + (size_t)NB*ML*VOC;
    decoder_persistent<<<NCTA, NTHR>>>(
        (const float*)d_in[0], (const float*)d_in[1],
        (const int*)d_in[2],   (const int*)d_in[3],
        (const float*)d_in[4],
        (const float*)d_in[5],  (const float*)d_in[6],
        (const float*)d_in[7],  (const float*)d_in[8],
        (const float*)d_in[9],  (const float*)d_in[10],
        (const float*)d_in[11], (const float*)d_in[12],
        (const float*)d_in[13], (const float*)d_in[14],
        (const float*)d_in[15], (const float*)d_in[16],
        (const float*)d_in[17], (const float*)d_in[18],
        (const float*)d_in[19], (const float*)d_in[20],
        preds, attns);
}